// round 10
// baseline (speedup 1.0000x reference)
#include <cuda_runtime.h>
#include <cstdint>

#define N_NODES 50000
#define N_EDGES 800000
#define N_GRAPHS 64
#define HID 64
#define HEADS 4
#define LAT 32
#define FEAT 256   // HEADS*HID

// ---------------- scratch (device globals; no allocation) ----------------
__device__ float g_xl[N_NODES * FEAT];      // 51.2 MB
__device__ float g_xr[N_NODES * FEAT];      // 51.2 MB
__device__ float g_h[N_NODES * HID];        // current node features
__device__ int   g_src[N_EDGES];
__device__ int   g_dst[N_EDGES];
__device__ int   g_esrc[N_EDGES];           // src ids, edges sorted by dst
__device__ int   g_deg[N_NODES];
__device__ int   g_scan[49 * 1024];         // 50176 >= N_NODES
__device__ int   g_bsum[64];
__device__ int   g_boff[64];
__device__ int   g_off[N_NODES + 1];        // CSR offsets by dst
__device__ int   g_cur[N_NODES];            // scatter cursors
__device__ float g_pooled[N_GRAPHS * HID];

// ---------------- prep: copy edge index, zero deg/pooled ----------------
__global__ void prep_kernel(const int* __restrict__ ei) {
    int i = blockIdx.x * 256 + threadIdx.x;
    if (i < N_EDGES) {
        g_src[i] = ei[i];
        g_dst[i] = ei[N_EDGES + i];
    }
    if (i < N_NODES) g_deg[i] = 0;
    if (i < N_GRAPHS * HID) g_pooled[i] = 0.f;
}

__global__ void hist_kernel() {
    int i = blockIdx.x * 256 + threadIdx.x;
    if (i < N_EDGES) atomicAdd(&g_deg[g_dst[i]], 1);
}

// ---- 3-kernel scan over g_deg -> g_off (exclusive), g_cur = g_off ----
__global__ void scan1_kernel() {
    __shared__ int sm[1024];
    int t = threadIdx.x, i = blockIdx.x * 1024 + t;
    int v = (i < N_NODES) ? g_deg[i] : 0;
    sm[t] = v;
    __syncthreads();
    for (int ofs = 1; ofs < 1024; ofs <<= 1) {
        int x = (t >= ofs) ? sm[t - ofs] : 0;
        __syncthreads();
        sm[t] += x;
        __syncthreads();
    }
    g_scan[i] = sm[t];
    if (t == 1023) g_bsum[blockIdx.x] = sm[1023];
}

__global__ void scan2_kernel() {
    __shared__ int sm[64];
    int t = threadIdx.x;
    int v = (t < 49) ? g_bsum[t] : 0;
    sm[t] = v;
    __syncthreads();
    for (int ofs = 1; ofs < 64; ofs <<= 1) {
        int x = (t >= ofs) ? sm[t - ofs] : 0;
        __syncthreads();
        sm[t] += x;
        __syncthreads();
    }
    g_boff[t] = sm[t] - v;   // exclusive block offset
}

__global__ void scan3_kernel() {
    int i = blockIdx.x * 256 + threadIdx.x;
    if (i >= N_NODES) return;
    g_off[i + 1] = g_scan[i] + g_boff[i >> 10];
    int o = (i == 0) ? 0 : (g_scan[i - 1] + g_boff[(i - 1) >> 10]);
    g_cur[i] = o;
    if (i == 0) g_off[0] = 0;
}

__global__ void scatter_kernel() {
    int e = blockIdx.x * 256 + threadIdx.x;
    if (e >= N_EDGES) return;
    int d = g_dst[e];
    int pos = atomicAdd(&g_cur[d], 1);
    g_esrc[pos] = g_src[e];
}

// ---------------- GEMM: O = A @ W via packed fma.rn.f32x2 ----------------
// Tile: 64 rows x 256 cols, 256 threads. Thread = (tx: 4 cols, ty: 16 rows).
// sAT holds A transposed [k][row]; adjacent rows give natural f32x2 pairs.
template <int K>
__global__ void __launch_bounds__(256)
gemm_kernel(const float* __restrict__ xext, int use_h,
            const float* __restrict__ W0, const float* __restrict__ W1) {
    const float* __restrict__ A = use_h ? g_h : xext;
    const float* __restrict__ W = blockIdx.y ? W1 : W0;
    float* __restrict__ O = blockIdx.y ? g_xr : g_xl;

    __shared__ float sAT[K][68];   // [k][row], 64 rows + 4 pad (16B-aligned rows)

    const int row0 = blockIdx.x * 64;
    const int tid = threadIdx.x;
    const int KQ = K / 4;

    // Load A[row0..row0+63][:] transposed. Adjacent tid -> adjacent row:
    // conflict-free STS (stride-1 in row index); LDG is 16B strided (2x sector
    // amplification, ~6us total across the launch -- acceptable).
    for (int idx = tid; idx < 64 * KQ; idx += 256) {
        int r = idx & 63, kq = idx >> 6;
        float4 v = make_float4(0.f, 0.f, 0.f, 0.f);
        if (row0 + r < N_NODES)
            v = *(const float4*)(A + (size_t)(row0 + r) * K + kq * 4);
        sAT[kq * 4 + 0][r] = v.x;
        sAT[kq * 4 + 1][r] = v.y;
        sAT[kq * 4 + 2][r] = v.z;
        sAT[kq * 4 + 3][r] = v.w;
    }
    __syncthreads();

    const int tx = tid & 63;   // cols [tx*4, tx*4+4)
    const int ty = tid >> 6;   // rows [ty*16, ty*16+16)

    unsigned long long accp[8][4];   // [row-pair][col], packed (even,odd) rows
#pragma unroll
    for (int i = 0; i < 8; i++)
#pragma unroll
        for (int c = 0; c < 4; c++) accp[i][c] = 0ull;

    const float* __restrict__ Wc = W + tx * 4;
#pragma unroll 2
    for (int k = 0; k < K; k++) {
        float4 w = *(const float4*)(Wc + (size_t)k * FEAT);
        unsigned long long wd[4];
        asm("mov.b64 %0, {%1,%1};" : "=l"(wd[0]) : "f"(w.x));
        asm("mov.b64 %0, {%1,%1};" : "=l"(wd[1]) : "f"(w.y));
        asm("mov.b64 %0, {%1,%1};" : "=l"(wd[2]) : "f"(w.z));
        asm("mov.b64 %0, {%1,%1};" : "=l"(wd[3]) : "f"(w.w));

        const ulonglong2* ap = (const ulonglong2*)(&sAT[k][ty * 16]);
        ulonglong2 p0 = ap[0], p1 = ap[1], p2 = ap[2], p3 = ap[3];
        unsigned long long a[8] = {p0.x, p0.y, p1.x, p1.y, p2.x, p2.y, p3.x, p3.y};
#pragma unroll
        for (int i = 0; i < 8; i++)
#pragma unroll
            for (int c = 0; c < 4; c++)
                asm("fma.rn.f32x2 %0, %1, %2, %0;"
                    : "+l"(accp[i][c]) : "l"(a[i]), "l"(wd[c]));
    }

#pragma unroll
    for (int i = 0; i < 8; i++) {
        float lo[4], hi[4];
#pragma unroll
        for (int c = 0; c < 4; c++)
            asm("mov.b64 {%0,%1}, %2;" : "=f"(lo[c]), "=f"(hi[c]) : "l"(accp[i][c]));
        int r_lo = row0 + ty * 16 + 2 * i;
        if (r_lo < N_NODES)
            *(float4*)(O + (size_t)r_lo * FEAT + tx * 4) =
                make_float4(lo[0], lo[1], lo[2], lo[3]);
        if (r_lo + 1 < N_NODES)
            *(float4*)(O + (size_t)(r_lo + 1) * FEAT + tx * 4) =
                make_float4(hi[0], hi[1], hi[2], hi[3]);
    }
}

// ---------------- fused GATv2 layer: warp per dst node, online softmax ----
// lane = grp*8 + gl; grp = head, lane covers features [grp*64 + gl*8, +8)
__global__ void __launch_bounds__(256)
fused_gat_kernel(const float* __restrict__ att, const float* __restrict__ bias,
                 const int* __restrict__ batch, int do_pool) {
    int d = blockIdx.x * 8 + (threadIdx.x >> 5);
    if (d >= N_NODES) return;
    int lane = threadIdx.x & 31;
    int grp = lane >> 3, gl = lane & 7;
    int fb = grp * 64 + gl * 8;

    const float4* __restrict__ xr4 = (const float4*)(g_xr + (size_t)d * FEAT + fb);
    float4 r0 = xr4[0], r1 = xr4[1];
    const float4* __restrict__ at4 = (const float4*)(att + fb);
    float4 t0 = at4[0], t1 = at4[1];

    float m = -1e30f, s = 0.f;
    float acc[8];
#pragma unroll
    for (int i = 0; i < 8; i++) acc[i] = 0.f;

    int e0 = g_off[d], e1 = g_off[d + 1];
    for (int p = e0; p < e1; p++) {
        int sn = __ldg(&g_esrc[p]);
        const float4* __restrict__ xl4 = (const float4*)(g_xl + (size_t)sn * FEAT + fb);
        float4 a0 = xl4[0], a1 = xl4[1];

        float L;
        {
            float e, q = 0.f;
            e = a0.x + r0.x; e = e > 0.f ? e : 0.2f * e; q += e * t0.x;
            e = a0.y + r0.y; e = e > 0.f ? e : 0.2f * e; q += e * t0.y;
            e = a0.z + r0.z; e = e > 0.f ? e : 0.2f * e; q += e * t0.z;
            e = a0.w + r0.w; e = e > 0.f ? e : 0.2f * e; q += e * t0.w;
            e = a1.x + r1.x; e = e > 0.f ? e : 0.2f * e; q += e * t1.x;
            e = a1.y + r1.y; e = e > 0.f ? e : 0.2f * e; q += e * t1.y;
            e = a1.z + r1.z; e = e > 0.f ? e : 0.2f * e; q += e * t1.z;
            e = a1.w + r1.w; e = e > 0.f ? e : 0.2f * e; q += e * t1.w;
            L = q;
        }
        // per-head logit: reduce within the 8-lane group
        L += __shfl_xor_sync(0xffffffffu, L, 1);
        L += __shfl_xor_sync(0xffffffffu, L, 2);
        L += __shfl_xor_sync(0xffffffffu, L, 4);

        // online softmax update
        float mn = fmaxf(m, L);
        float sc = __expf(m - mn);
        float pw = __expf(L - mn);
        m = mn;
        s = s * sc + pw;
        acc[0] = acc[0] * sc + pw * a0.x;
        acc[1] = acc[1] * sc + pw * a0.y;
        acc[2] = acc[2] * sc + pw * a0.z;
        acc[3] = acc[3] * sc + pw * a0.w;
        acc[4] = acc[4] * sc + pw * a1.x;
        acc[5] = acc[5] * sc + pw * a1.y;
        acc[6] = acc[6] * sc + pw * a1.z;
        acc[7] = acc[7] * sc + pw * a1.w;
    }

    // per-head normalize + fold head-mean, then sum across heads
    float inv = 0.25f / (s + 1e-16f);
#pragma unroll
    for (int i = 0; i < 8; i++) {
        float v = acc[i] * inv;
        v += __shfl_xor_sync(0xffffffffu, v, 8);
        v += __shfl_xor_sync(0xffffffffu, v, 16);
        acc[i] = v;
    }

    if (grp == 0) {
        float out[8];
#pragma unroll
        for (int i = 0; i < 8; i++) {
            float v = acc[i] + bias[gl * 8 + i];
            out[i] = v > 0.f ? v : 0.1f * v;
        }
        float4* hp = (float4*)(g_h + (size_t)d * HID + gl * 8);
        hp[0] = make_float4(out[0], out[1], out[2], out[3]);
        hp[1] = make_float4(out[4], out[5], out[6], out[7]);
        if (do_pool) {
            int gph = batch[d];
            float* pp = g_pooled + gph * HID + gl * 8;
#pragma unroll
            for (int i = 0; i < 8; i++) atomicAdd(pp + i, out[i]);
        }
    }
}

// ---------------- BN over graphs + FC, single block ----------------
__global__ void bn_fc_kernel(const float* __restrict__ gamma,
                             const float* __restrict__ beta,
                             const float* __restrict__ fcW,
                             const float* __restrict__ fcb,
                             float* __restrict__ out) {
    __shared__ float snorm[N_GRAPHS * HID];
    int tid = threadIdx.x;
    if (tid < HID) {
        float s = 0.f;
        for (int g = 0; g < N_GRAPHS; g++) s += g_pooled[g * HID + tid];
        float mean = s * (1.f / N_GRAPHS);
        float vs = 0.f;
        for (int g = 0; g < N_GRAPHS; g++) {
            float dlt = g_pooled[g * HID + tid] - mean;
            vs += dlt * dlt;
        }
        float inv = rsqrtf(vs * (1.f / N_GRAPHS) + 1e-5f);
        float ga = gamma[tid] * inv, be = beta[tid];
        for (int g = 0; g < N_GRAPHS; g++)
            snorm[g * HID + tid] = (g_pooled[g * HID + tid] - mean) * ga + be;
    }
    __syncthreads();
    for (int i = tid; i < N_GRAPHS * LAT; i += blockDim.x) {
        int g = i >> 5, l = i & 31;
        float s = fcb[l];
#pragma unroll
        for (int d = 0; d < HID; d++) s += snorm[g * HID + d] * fcW[l * HID + d];
        out[i] = s;
    }
}

// ---------------- launch ----------------
// Launch order puts gemm<128> at launch index 3 so the ncu capture
// (observed to grab index 3) profiles the dominant kernel next round.
extern "C" void kernel_launch(void* const* d_in, const int* in_sizes, int n_in,
                              void* d_out, int out_size) {
    const float* x = (const float*)d_in[0];
    const int* ei = (const int*)d_in[1];
    const int* batch = (const int*)d_in[2];
    const float* Wl[3]  = {(const float*)d_in[3],  (const float*)d_in[7],  (const float*)d_in[11]};
    const float* Wr[3]  = {(const float*)d_in[4],  (const float*)d_in[8],  (const float*)d_in[12]};
    const float* att[3] = {(const float*)d_in[5],  (const float*)d_in[9],  (const float*)d_in[13]};
    const float* bb[3]  = {(const float*)d_in[6],  (const float*)d_in[10], (const float*)d_in[14]};
    const float* gamma = (const float*)d_in[15];
    const float* beta  = (const float*)d_in[16];
    const float* fcW   = (const float*)d_in[17];
    const float* fcb   = (const float*)d_in[18];
    float* out = (float*)d_out;

    const int eb = (N_EDGES + 255) / 256;           // 3125
    const int gemm_bx = (N_NODES + 63) / 64;        // 782
    const int gat_b = (N_NODES + 7) / 8;            // warp per node

    prep_kernel<<<eb, 256>>>(ei);                               // 0
    hist_kernel<<<eb, 256>>>();                                 // 1
    scan1_kernel<<<49, 1024>>>();                               // 2
    gemm_kernel<128><<<dim3(gemm_bx, 2), 256>>>(x, 0, Wl[0], Wr[0]);  // 3 <- profiled
    scan2_kernel<<<1, 64>>>();                                  // 4
    scan3_kernel<<<(N_NODES + 255) / 256, 256>>>();             // 5
    scatter_kernel<<<eb, 256>>>();                              // 6

    fused_gat_kernel<<<gat_b, 256>>>(att[0], bb[0], batch, 0);  // 7

    for (int l = 1; l < 3; l++) {
        gemm_kernel<64><<<dim3(gemm_bx, 2), 256>>>(nullptr, 1, Wl[l], Wr[l]);
        fused_gat_kernel<<<gat_b, 256>>>(att[l], bb[l], batch, l == 2 ? 1 : 0);
    }

    bn_fc_kernel<<<1, 256>>>(gamma, beta, fcW, fcb, out);
}